// round 17
// baseline (speedup 1.0000x reference)
#include <cuda_runtime.h>
#include <cuda_bf16.h>
#include <stdint.h>
#include <math.h>
#include <float.h>

#define Nn   2048
#define Cc   1024
#define Hh   16
#define Dd   64
#define F3   3072
#define NNel (2048u*2048u)
#define OUT_OFF (2048*1024)
#define SA   40
#define GTILE (128 * SA * 2)            // bytes per 128-row A slab (BK=32 +pad)
#define GSM   (2 * 4 * GTILE)           // gemm: 2 stages x 4 arrays = 81920 B
#define PV_BROW 72                      // pv B slab row stride in bf16 (64 d + pad 8)
#define PV_BT (32 * PV_BROW * 2)        // pv B slab: 32 k-rows -> 4608 B
#define PV_STAGE (2 * GTILE + 2 * PV_BT)
#define PV_SM (2 * PV_STAGE)            // 59392 B

typedef __nv_bfloat16 bf16;
typedef __nv_bfloat162 bf162;

// -------- device scratch --------
__device__ float g_q[Hh * Nn * Dd];
__device__ float g_k[Hh * Nn * Dd];
__device__ float g_v[Hh * Nn * Dd];
__device__ float g_S[(size_t)Hh * NNel];
__device__ float g_M[(size_t)Hh * NNel];
__device__ float g_vsum[Hh * Dd];
__device__ float g_vsump[Hh * 16 * Dd];
__device__ float g_pmax[Hh * Nn * 8];
__device__ float g_psum[Hh * Nn * 8];
__device__ float g_rmax[Hh * Nn];
__device__ float g_rinv[Hh * Nn];

__device__ bf16 g_xh[Nn * Cc];
__device__ bf16 g_xl[Nn * Cc];
__device__ bf16 g_wqh[F3 * Cc];
__device__ bf16 g_wql[F3 * Cc];
__device__ bf16 g_woh[Cc * Cc];
__device__ bf16 g_wol[Cc * Cc];
__device__ bf16 g_qh[Hh * Nn * Dd];
__device__ bf16 g_ql[Hh * Nn * Dd];
__device__ bf16 g_kh[Hh * Nn * Dd];
__device__ bf16 g_kl[Hh * Nn * Dd];
__device__ bf16 g_vh[Hh * Nn * Dd];     // V bf16 splits, natural [h][n][d]
__device__ bf16 g_vl[Hh * Nn * Dd];
__device__ bf16 g_Ph[(size_t)Hh * NNel];
__device__ bf16 g_Pl[(size_t)Hh * NNel];
__device__ bf16 g_atth[Nn * Cc];
__device__ bf16 g_attl[Nn * Cc];

// ---------------- helpers ----------------
__device__ __forceinline__ uint32_t cvta_s(const void* p) {
    return (uint32_t)__cvta_generic_to_shared(p);
}

__device__ __forceinline__ void ldsm4(uint32_t* r, uint32_t a) {
    asm volatile("ldmatrix.sync.aligned.m8n8.x4.shared.b16 {%0,%1,%2,%3}, [%4];"
        : "=r"(r[0]), "=r"(r[1]), "=r"(r[2]), "=r"(r[3]) : "r"(a));
}

__device__ __forceinline__ void ldsm4t(uint32_t* r, uint32_t a) {
    asm volatile("ldmatrix.sync.aligned.m8n8.x4.trans.shared.b16 {%0,%1,%2,%3}, [%4];"
        : "=r"(r[0]), "=r"(r[1]), "=r"(r[2]), "=r"(r[3]) : "r"(a));
}

__device__ __forceinline__ void mma_bf16(float* d, const uint32_t* a, const uint32_t* b) {
    asm volatile("mma.sync.aligned.m16n8k16.row.col.f32.bf16.bf16.f32 "
        "{%0,%1,%2,%3}, {%4,%5,%6,%7}, {%8,%9}, {%0,%1,%2,%3};"
        : "+f"(d[0]), "+f"(d[1]), "+f"(d[2]), "+f"(d[3])
        : "r"(a[0]), "r"(a[1]), "r"(a[2]), "r"(a[3]), "r"(b[0]), "r"(b[1]));
}

__device__ __forceinline__ void split1(float v, bf16* hp, bf16* lp) {
    bf16 hh = __float2bfloat16(v);
    *hp = hh;
    *lp = __float2bfloat16(v - __bfloat162float(hh));
}

__device__ __forceinline__ void cp16r(uint32_t sa, const void* g) {
    asm volatile("cp.async.cg.shared.global [%0], [%1], 16;" :: "r"(sa), "l"(g) : "memory");
}
__device__ __forceinline__ void cp_commit() { asm volatile("cp.async.commit_group;"); }
__device__ __forceinline__ void cp_wait1()  { asm volatile("cp.async.wait_group 1;"); }
__device__ __forceinline__ void cp_wait0()  { asm volatile("cp.async.wait_group 0;"); }

// scatter one qkv element (gemm epilogue mode 1) — no transposed stores
__device__ __forceinline__ void scat1(int n, int f, float v, float* __restrict__ dout)
{
    int s = f % 3;
    int hd = f / 3;
    int h = hd >> 6;
    int d = hd & 63;
    size_t qoff = ((size_t)h * Nn + n) * 64 + d;
    if (s == 0) {
        g_q[qoff] = v;
    } else if (s == 1) {
        g_k[qoff] = v;
        dout[OUT_OFF + qoff] = v;
    } else {
        g_v[qoff] = v;
        dout[OUT_OFF + (size_t)Hh * Nn * Dd + qoff] = v;
        bf16 hv, lv;
        split1(v, &hv, &lv);
        g_vh[qoff] = hv;
        g_vl[qoff] = lv;
    }
}

// ============================================================
// split fp32 -> (hi, lo) bf16, vectorized x4
// ============================================================
__global__ void split4(const float4* __restrict__ src,
                       bf162* __restrict__ hh, bf162* __restrict__ ll, int n4)
{
    int i = blockIdx.x * 256 + threadIdx.x;
    if (i >= n4) return;
    float4 v = src[i];
    bf16 h0, l0, h1, l1, h2, l2, h3, l3;
    split1(v.x, &h0, &l0);
    split1(v.y, &h1, &l1);
    split1(v.z, &h2, &l2);
    split1(v.w, &h3, &l3);
    hh[2 * i]     = __halves2bfloat162(h0, h1);
    hh[2 * i + 1] = __halves2bfloat162(h2, h3);
    ll[2 * i]     = __halves2bfloat162(l0, l1);
    ll[2 * i + 1] = __halves2bfloat162(l2, l3);
}

// ============================================================
// split-bf16 NT GEMM, BK=32, 2-stage cp.async double buffer.
// mode 0: C[m][n] fp32 store.  mode 1: qkv scatter epilogue.
// ============================================================
__global__ void __launch_bounds__(256, 2) gemm_nt_bf16(
    const bf16* __restrict__ Ah, const bf16* __restrict__ Al,
    const bf16* __restrict__ Bh, const bf16* __restrict__ Bl,
    float* __restrict__ C, float* __restrict__ dout, int mode,
    int M, int N, int K)
{
    extern __shared__ char dsm[];
    const uint32_t sbase = cvta_s(dsm);
    const int tid = threadIdx.x;
    const int lane = tid & 31;
    const int wid = tid >> 5;
    const int bm = blockIdx.y * 128;
    const int bn = blockIdx.x * 128;
    const int wr = wid >> 2;
    const int wc = wid & 3;

    float acc[4][4][4];
#pragma unroll
    for (int a = 0; a < 4; a++)
#pragma unroll
        for (int b = 0; b < 4; b++)
#pragma unroll
            for (int c = 0; c < 4; c++) acc[a][b][c] = 0.f;

    const bf16* srcs[4];
    srcs[0] = Ah;
    srcs[1] = Al;
    srcs[2] = Bh;
    srcs[3] = Bl;

    auto do_load = [&](int st, int k0) {
        uint32_t sb = sbase + (uint32_t)st * (4u * GTILE);
#pragma unroll
        for (int arr = 0; arr < 4; arr++) {
            const bf16* src = srcs[arr];
            int rbase = (arr < 2) ? bm : bn;
#pragma unroll
            for (int q = tid; q < 512; q += 256) {
                int row = q >> 2;
                int c8 = (q & 3) << 3;
                uint32_t sa = sb + (uint32_t)arr * GTILE + (uint32_t)(row * (SA * 2) + c8 * 2);
                cp16r(sa, src + (size_t)(rbase + row) * K + k0 + c8);
            }
        }
        cp_commit();
    };

    do_load(0, 0);
    const int S = K >> 5;
    for (int s = 0; s < S; s++) {
        int st = s & 1;
        if (s + 1 < S) {
            do_load(st ^ 1, (s + 1) << 5);
            cp_wait1();
        } else {
            cp_wait0();
        }
        __syncthreads();
        uint32_t sb = sbase + (uint32_t)st * (4u * GTILE);
        uint32_t aAh = sb + 0u * GTILE;
        uint32_t aAl = sb + 1u * GTILE;
        uint32_t aBh = sb + 2u * GTILE;
        uint32_t aBl = sb + 3u * GTILE;
#pragma unroll
        for (int ks = 0; ks < 32; ks += 16) {
            uint32_t afh[4][4];
            uint32_t afl[4][4];
            uint32_t bfh[4][2];
            uint32_t bfl[4][2];
            int arow = lane & 15;
            int acol = ks + ((lane >> 4) << 3);
#pragma unroll
            for (int mt = 0; mt < 4; mt++) {
                uint32_t ro = (uint32_t)((wr * 64 + mt * 16 + arow) * (SA * 2) + acol * 2);
                ldsm4(afh[mt], aAh + ro);
                ldsm4(afl[mt], aAl + ro);
            }
#pragma unroll
            for (int np = 0; np < 2; np++) {
                uint32_t ro = (uint32_t)((wc * 32 + np * 16 + arow) * (SA * 2) + acol * 2);
                uint32_t tr[4];
                ldsm4(tr, aBh + ro);
                bfh[np * 2][0] = tr[0];
                bfh[np * 2][1] = tr[2];
                bfh[np * 2 + 1][0] = tr[1];
                bfh[np * 2 + 1][1] = tr[3];
                ldsm4(tr, aBl + ro);
                bfl[np * 2][0] = tr[0];
                bfl[np * 2][1] = tr[2];
                bfl[np * 2 + 1][0] = tr[1];
                bfl[np * 2 + 1][1] = tr[3];
            }
#pragma unroll
            for (int mt = 0; mt < 4; mt++) {
#pragma unroll
                for (int nt = 0; nt < 4; nt++) {
                    mma_bf16(acc[mt][nt], afh[mt], bfh[nt]);
                    mma_bf16(acc[mt][nt], afh[mt], bfl[nt]);
                    mma_bf16(acc[mt][nt], afl[mt], bfh[nt]);
                }
            }
        }
        __syncthreads();
    }
    int gr = lane >> 2;
    int qd = lane & 3;
    if (mode == 0) {
#pragma unroll
        for (int mt = 0; mt < 4; mt++) {
#pragma unroll
            for (int nt = 0; nt < 4; nt++) {
                int m = bm + wr * 64 + mt * 16 + gr;
                int n = bn + wc * 32 + nt * 8 + qd * 2;
                *(float2*)&C[(size_t)m * N + n]       = make_float2(acc[mt][nt][0], acc[mt][nt][1]);
                *(float2*)&C[(size_t)(m + 8) * N + n] = make_float2(acc[mt][nt][2], acc[mt][nt][3]);
            }
        }
    } else {
#pragma unroll
        for (int mt = 0; mt < 4; mt++) {
#pragma unroll
            for (int nt = 0; nt < 4; nt++) {
                int m0 = bm + wr * 64 + mt * 16 + gr;
                int f0 = bn + wc * 32 + nt * 8 + qd * 2;
                scat1(m0,     f0,     acc[mt][nt][0], dout);
                scat1(m0,     f0 + 1, acc[mt][nt][1], dout);
                scat1(m0 + 8, f0,     acc[mt][nt][2], dout);
                scat1(m0 + 8, f0 + 1, acc[mt][nt][3], dout);
            }
        }
    }
}

// ============================================================
// Scores: per-head causal lower-tri 128x128 tiles. K=64. (static, BK=32)
// ============================================================
__global__ void __launch_bounds__(256) scores_bf16(const float* __restrict__ tscale)
{
    __shared__ bf16 sAh[128 * SA];
    __shared__ bf16 sAl[128 * SA];
    __shared__ bf16 sBh[128 * SA];
    __shared__ bf16 sBl[128 * SA];
    const int tid = threadIdx.x;
    const int lane = tid & 31;
    const int wid = tid >> 5;
    int hh = blockIdx.y;
    int tb = blockIdx.x;
    int bi = (int)((sqrtf(8.f * tb + 1.f) - 1.f) * 0.5f);
    while ((bi + 1) * (bi + 2) / 2 <= tb) bi++;
    while (bi * (bi + 1) / 2 > tb) bi--;
    int bj = tb - bi * (bi + 1) / 2;
    const int bm = bi * 128;
    const int bn = bj * 128;
    const int wr = wid >> 2;
    const int wc = wid & 3;

    const bf16* Ah = g_qh + (size_t)hh * Nn * Dd;
    const bf16* Al = g_ql + (size_t)hh * Nn * Dd;
    const bf16* Bh = g_kh + (size_t)hh * Nn * Dd;
    const bf16* Bl = g_kl + (size_t)hh * Nn * Dd;
    float* C = g_S + (size_t)hh * NNel;

    float acc[4][4][4];
#pragma unroll
    for (int a = 0; a < 4; a++)
#pragma unroll
        for (int b = 0; b < 4; b++)
#pragma unroll
            for (int c = 0; c < 4; c++) acc[a][b][c] = 0.f;

    for (int k0 = 0; k0 < Dd; k0 += 32) {
#pragma unroll
        for (int q = tid; q < 512; q += 256) {
            int row = q >> 2;
            int c8 = (q & 3) << 3;
            size_t ga = (size_t)(bm + row) * Dd + k0 + c8;
            size_t gb = (size_t)(bn + row) * Dd + k0 + c8;
            *(uint4*)&sAh[row * SA + c8] = *(const uint4*)&Ah[ga];
            *(uint4*)&sAl[row * SA + c8] = *(const uint4*)&Al[ga];
            *(uint4*)&sBh[row * SA + c8] = *(const uint4*)&Bh[gb];
            *(uint4*)&sBl[row * SA + c8] = *(const uint4*)&Bl[gb];
        }
        __syncthreads();
#pragma unroll
        for (int ks = 0; ks < 32; ks += 16) {
            uint32_t afh[4][4];
            uint32_t afl[4][4];
            uint32_t bfh[4][2];
            uint32_t bfl[4][2];
            int arow = lane & 15;
            int acol = ks + ((lane >> 4) << 3);
#pragma unroll
            for (int mt = 0; mt < 4; mt++) {
                ldsm4(afh[mt], cvta_s(&sAh[(wr * 64 + mt * 16 + arow) * SA + acol]));
                ldsm4(afl[mt], cvta_s(&sAl[(wr * 64 + mt * 16 + arow) * SA + acol]));
            }
#pragma unroll
            for (int np = 0; np < 2; np++) {
                uint32_t tr[4];
                ldsm4(tr, cvta_s(&sBh[(wc * 32 + np * 16 + arow) * SA + acol]));
                bfh[np * 2][0] = tr[0];
                bfh[np * 2][1] = tr[2];
                bfh[np * 2 + 1][0] = tr[1];
                bfh[np * 2 + 1][1] = tr[3];
                ldsm4(tr, cvta_s(&sBl[(wc * 32 + np * 16 + arow) * SA + acol]));
                bfl[np * 2][0] = tr[0];
                bfl[np * 2][1] = tr[2];
                bfl[np * 2 + 1][0] = tr[1];
                bfl[np * 2 + 1][1] = tr[3];
            }
#pragma unroll
            for (int mt = 0; mt < 4; mt++) {
#pragma unroll
                for (int nt = 0; nt < 4; nt++) {
                    mma_bf16(acc[mt][nt], afh[mt], bfh[nt]);
                    mma_bf16(acc[mt][nt], afh[mt], bfl[nt]);
                    mma_bf16(acc[mt][nt], afl[mt], bfh[nt]);
                }
            }
        }
        __syncthreads();
    }
    float al = tscale[0];
    int gr = lane >> 2;
    int qd = lane & 3;
#pragma unroll
    for (int mt = 0; mt < 4; mt++) {
#pragma unroll
        for (int nt = 0; nt < 4; nt++) {
            int m = bm + wr * 64 + mt * 16 + gr;
            int n = bn + wc * 32 + nt * 8 + qd * 2;
            *(float2*)&C[(size_t)m * Nn + n]       = make_float2(acc[mt][nt][0] * al, acc[mt][nt][1] * al);
            *(float2*)&C[(size_t)(m + 8) * Nn + n] = make_float2(acc[mt][nt][2] * al, acc[mt][nt][3] * al);
        }
    }
}

// ============================================================
// PV, BK=32, 2-stage cp.async pipeline. V loaded natural [j][d],
// B fragments produced via ldmatrix.trans.
// ============================================================
__global__ void __launch_bounds__(256, 2) pv_bf16(const float* __restrict__ bpost)
{
    extern __shared__ char dsm[];
    const uint32_t sbase = cvta_s(dsm);
    const int tid = threadIdx.x;
    const int lane = tid & 31;
    const int wid = tid >> 5;
    int hh = blockIdx.y;
    const int bm = blockIdx.x * 128;
    const int wr = wid >> 1;
    const int wc = wid & 1;

    const bf16* Ah = g_Ph + (size_t)hh * NNel;
    const bf16* Al = g_Pl + (size_t)hh * NNel;
    const bf16* Bh = g_vh + (size_t)hh * Nn * Dd;
    const bf16* Bl = g_vl + (size_t)hh * Nn * Dd;

    float acc[2][4][4];
#pragma unroll
    for (int a = 0; a < 2; a++)
#pragma unroll
        for (int b = 0; b < 4; b++)
#pragma unroll
            for (int c = 0; c < 4; c++) acc[a][b][c] = 0.f;

    auto pv_load = [&](int st, int k0) {
        uint32_t sb = sbase + (uint32_t)st * PV_STAGE;
#pragma unroll
        for (int q = tid; q < 512; q += 256) {
            int row = q >> 2;
            int c8 = (q & 3) << 3;
            uint32_t ro = (uint32_t)(row * (SA * 2) + c8 * 2);
            size_t ga = (size_t)(bm + row) * Nn + k0 + c8;
            cp16r(sb + ro, Ah + ga);
            cp16r(sb + GTILE + ro, Al + ga);
        }
        {
            // B: 32 k-rows x 64 d, natural layout, 16B chunks
            int row = tid >> 3;        // 0..31
            int c16 = tid & 7;         // 0..7 (8 chunks of 8 bf16 per row)
            uint32_t ro = (uint32_t)(row * (PV_BROW * 2) + c16 * 16);
            size_t gb = (size_t)(k0 + row) * Dd + c16 * 8;
            cp16r(sb + 2u * GTILE + ro, Bh + gb);
            cp16r(sb + 2u * GTILE + PV_BT + ro, Bl + gb);
        }
        cp_commit();
    };

    pv_load(0, 0);
    const int S = (bm + 128) >> 5;
    for (int s = 0; s < S; s++) {
        int st = s & 1;
        if (s + 1 < S) {
            pv_load(st ^ 1, (s + 1) << 5);
            cp_wait1();
        } else {
            cp_wait0();
        }
        __syncthreads();
        uint32_t sb = sbase + (uint32_t)st * PV_STAGE;
        uint32_t aAh = sb;
        uint32_t aAl = sb + GTILE;
        uint32_t aBh = sb + 2u * GTILE;
        uint32_t aBl = sb + 2u * GTILE + PV_BT;
#pragma unroll
        for (int ks = 0; ks < 32; ks += 16) {
            uint32_t afh[2][4];
            uint32_t afl[2][4];
            uint32_t bfh[4][2];
            uint32_t bfl[4][2];
            int arow = lane & 15;
            int acol = ks + ((lane >> 4) << 3);
#pragma unroll
            for (int mt = 0; mt < 2; mt++) {
                uint32_t ro = (uint32_t)((wr * 32 + mt * 16 + arow) * (SA * 2) + acol * 2);
                ldsm4(afh[mt], aAh + ro);
                ldsm4(afl[mt], aAl + ro);
            }
            // B via ldmatrix.trans: mats 0..3 = [k 0-7/8-15][n 0-7/8-15] src blocks
            int matid = lane >> 3;
            int r8 = lane & 7;
            int krow = ks + ((matid >> 1) & 1) * 8 + r8;
#pragma unroll
            for (int np = 0; np < 2; np++) {
                int nb = wc * 32 + np * 16 + (matid & 1) * 8;
                uint32_t ro = (uint32_t)(krow * (PV_BROW * 2) + nb * 2);
                uint32_t tr[4];
                ldsm4t(tr, aBh + ro);
                bfh[np * 2][0] = tr[0];
                bfh[np * 2][1] = tr[2];
                bfh[np * 2 + 1][0] = tr[1];
                bfh[np * 2 + 1][1] = tr[3];
                ldsm4t(tr, aBl + ro);
                bfl[np * 2][0] = tr[0];
                bfl[np * 2][1] = tr[2];
                bfl[np * 2 + 1][0] = tr[1];
                bfl[np * 2 + 1][1] = tr[3];
            }
#pragma unroll
            for (int mt = 0; mt < 2; mt++) {
#pragma unroll
                for (int nt = 0; nt < 4; nt++) {
                    mma_bf16(acc[mt][nt], afh[mt], bfh[nt]);
                    mma_bf16(acc[mt][nt], afh[mt], bfl[nt]);
                    mma_bf16(acc[mt][nt], afl[mt], bfh[nt]);
                }
            }
        }
        __syncthreads();
    }
    float bp = bpost[hh];
    int gr = lane >> 2;
    int qd = lane & 3;
#pragma unroll
    for (int mt = 0; mt < 2; mt++) {
#pragma unroll
        for (int nt = 0; nt < 4; nt++) {
            int m = bm + wr * 32 + mt * 16 + gr;
            int d = wc * 32 + nt * 8 + qd * 2;
            float vs0 = g_vsum[hh * 64 + d];
            float vs1 = g_vsum[hh * 64 + d + 1];
            float v0 = acc[mt][nt][0] + bp * vs0;
            float v1 = acc[mt][nt][1] + bp * vs1;
            float v2 = acc[mt][nt][2] + bp * vs0;
            float v3 = acc[mt][nt][3] + bp * vs1;
            bf16 h0, l0, h1, l1;
            split1(v0, &h0, &l0);
            split1(v1, &h1, &l1);
            *(bf162*)&g_atth[(size_t)m * Cc + hh * 64 + d] = __halves2bfloat162(h0, h1);
            *(bf162*)&g_attl[(size_t)m * Cc + hh * 64 + d] = __halves2bfloat162(l0, l1);
            split1(v2, &h0, &l0);
            split1(v3, &h1, &l1);
            *(bf162*)&g_atth[(size_t)(m + 8) * Cc + hh * 64 + d] = __halves2bfloat162(h0, h1);
            *(bf162*)&g_attl[(size_t)(m + 8) * Cc + hh * 64 + d] = __halves2bfloat162(l0, l1);
        }
    }
}

// ============================================================
// L2-normalize q,k rows; write bf16 splits
// ============================================================
__global__ void l2norm_k()
{
    int gidx = blockIdx.x * 256 + threadIdx.x;
    int warp = gidx >> 5;
    int lane = gidx & 31;
    bool isq = warp < Hh * Nn;
    size_t roff = (size_t)(isq ? warp : warp - Hh * Nn) * 64;
    const float* base = (isq ? g_q : g_k) + roff;
    float2 v = *(const float2*)(base + lane * 2);
    float ss = v.x * v.x + v.y * v.y;
#pragma unroll
    for (int o = 16; o; o >>= 1) ss += __shfl_xor_sync(0xffffffffu, ss, o);
    float inv = 1.f / fmaxf(sqrtf(ss), 1e-12f);
    v.x *= inv;
    v.y *= inv;
    bf16 h0, l0, h1, l1;
    split1(v.x, &h0, &l0);
    split1(v.y, &h1, &l1);
    bf16* dh = (isq ? g_qh : g_kh) + roff;
    bf16* dl = (isq ? g_ql : g_kl) + roff;
    *(bf162*)(dh + lane * 2) = __halves2bfloat162(h0, h1);
    *(bf162*)(dl + lane * 2) = __halves2bfloat162(l0, l1);
}

// ============================================================
// vsum partials + reduce
// ============================================================
__global__ void vsum_part()
{
    __shared__ float sr[256];
    int h = blockIdx.x;
    int c = blockIdx.y;
    int tid = threadIdx.x;
    int d = tid & 63;
    int p = tid >> 6;
    float s = 0.f;
    for (int n = c * 128 + p; n < (c + 1) * 128; n += 4)
        s += g_v[((size_t)h * Nn + n) * 64 + d];
    sr[tid] = s;
    __syncthreads();
    if (p == 0)
        g_vsump[(h * 16 + c) * 64 + d] = sr[d] + sr[64 + d] + sr[128 + d] + sr[192 + d];
}

__global__ void vsum_red()
{
    int h = blockIdx.x;
    int d = threadIdx.x;
    float s = 0.f;
    for (int c = 0; c < 16; c++) s += g_vsump[(h * 16 + c) * 64 + d];
    g_vsum[h * 64 + d] = s;
}

// ============================================================
// Talking-heads PRE + b_pre + pos_bias + per-block softmax partials
// ============================================================
__global__ void premix_k(const float* __restrict__ Wpre,
                         const float* __restrict__ bpre,
                         const float* __restrict__ pb)
{
    __shared__ float w[256];
    __shared__ float bb[16];
    __shared__ float rbuf[16 * 256];
    __shared__ float gmax[16];
    int tid = threadIdx.x;
    int i = blockIdx.y;
    int jb = blockIdx.x;
    if (jb * 256 > i) return;
    w[tid] = Wpre[tid];
    if (tid < 16) bb[tid] = bpre[tid];
    __syncthreads();
    int j = jb * 256 + tid;
    bool valid = (j <= i);
    size_t off = (size_t)i * Nn + j;
    float m[16];
    if (valid) {
        float sarr[16];
#pragma unroll
        for (int h = 0; h < 16; h++) sarr[h] = g_S[(size_t)h * NNel + off];
#pragma unroll
        for (int g = 0; g < 16; g++) {
            float mm = bb[g] + pb[(size_t)g * NNel + off];
#pragma unroll
            for (int h = 0; h < 16; h++) mm += w[g * 16 + h] * sarr[h];
            m[g] = mm;
            g_M[(size_t)g * NNel + off] = mm;
        }
    } else {
#pragma unroll
        for (int g = 0; g < 16; g++) m[g] = -FLT_MAX;
    }
#pragma unroll
    for (int g = 0; g < 16; g++) rbuf[g * 256 + tid] = m[g];
    __syncthreads();
    int wd = tid >> 5;
    int lane = tid & 31;
#pragma unroll
    for (int gg = wd * 2; gg < wd * 2 + 2; gg++) {
        float v = rbuf[gg * 256 + lane];
#pragma unroll
        for (int r = 1; r < 8; r++) v = fmaxf(v, rbuf[gg * 256 + lane + r * 32]);
#pragma unroll
        for (int o = 16; o; o >>= 1) v = fmaxf(v, __shfl_xor_sync(0xffffffffu, v, o));
        if (lane == 0) gmax[gg] = v;
    }
    __syncthreads();
#pragma unroll
    for (int g = 0; g < 16; g++) rbuf[g * 256 + tid] = __expf(m[g] - gmax[g]);
    __syncthreads();
#pragma unroll
    for (int gg = wd * 2; gg < wd * 2 + 2; gg++) {
        float v = rbuf[gg * 256 + lane];
#pragma unroll
        for (int r = 1; r < 8; r++) v += rbuf[gg * 256 + lane + r * 32];
#pragma unroll
        for (int o = 16; o; o >>= 1) v += __shfl_xor_sync(0xffffffffu, v, o);
        if (lane == 0) {
            g_pmax[((size_t)gg * Nn + i) * 8 + jb] = gmax[gg];
            g_psum[((size_t)gg * Nn + i) * 8 + jb] = v;
        }
    }
}

// ============================================================
// Combine per-block partials -> row (max, 1/Z)
// ============================================================
__global__ void rowred_k()
{
    int r = blockIdx.x * 256 + threadIdx.x;
    int i = r & (Nn - 1);
    int nb = (i >> 8) + 1;
    float mx = -FLT_MAX;
    for (int b = 0; b < nb; b++) mx = fmaxf(mx, g_pmax[(size_t)r * 8 + b]);
    float Z = 0.f;
    for (int b = 0; b < nb; b++) Z += g_psum[(size_t)r * 8 + b] * __expf(g_pmax[(size_t)r * 8 + b] - mx);
    g_rmax[r] = mx;
    g_rinv[r] = 1.f / Z;
}

// ============================================================
// Normalize + talking-heads POST -> split-bf16 Ph/Pl; zero diag-block.
// ============================================================
__global__ void postmix_k(const float* __restrict__ Wpost)
{
    __shared__ float w[256];
    __shared__ float smx[16];
    __shared__ float sin_[16];
    int tid = threadIdx.x;
    int i = blockIdx.y;
    w[tid] = Wpost[tid];
    if (tid < 16) {
        smx[tid] = g_rmax[tid * Nn + i];
        sin_[tid] = g_rinv[tid * Nn + i];
    }
    __syncthreads();
    int j = blockIdx.x * 256 + tid;
    size_t off = (size_t)i * Nn + j;
    if (j > i) {
        if ((j >> 7) == (i >> 7)) {
            bf16 z = __float2bfloat16(0.f);
#pragma unroll
            for (int g = 0; g < 16; g++) {
                g_Ph[(size_t)g * NNel + off] = z;
                g_Pl[(size_t)g * NNel + off] = z;
            }
        }
        return;
    }
    float p[16];
#pragma unroll
    for (int h = 0; h < 16; h++)
        p[h] = __expf(g_M[(size_t)h * NNel + off] - smx[h]) * sin_[h];
#pragma unroll
    for (int g = 0; g < 16; g++) {
        float m = 0.f;
#pragma unroll
        for (int h = 0; h < 16; h++) m += w[g * 16 + h] * p[h];
        bf16 hv, lv;
        split1(m, &hv, &lv);
        g_Ph[(size_t)g * NNel + off] = hv;
        g_Pl[(size_t)g * NNel + off] = lv;
    }
}

// ============================================================
extern "C" void kernel_launch(void* const* d_in, const int* in_sizes, int n_in,
                              void* d_out, int out_size)
{
    const float* x      = (const float*)d_in[0];
    const float* pb     = (const float*)d_in[1];
    const float* Wqkv   = (const float*)d_in[3];
    const float* Wout   = (const float*)d_in[4];
    const float* tscale = (const float*)d_in[5];
    const float* Wpre   = (const float*)d_in[6];
    const float* bpre   = (const float*)d_in[7];
    const float* Wpost  = (const float*)d_in[8];
    const float* bpost  = (const float*)d_in[9];
    float* out = (float*)d_out;

    bf16* xh;
    bf16* xl;
    bf16* wqh;
    bf16* wql;
    bf16* woh;
    bf16* wol;
    bf16* atth;
    bf16* attl;
    cudaGetSymbolAddress((void**)&xh, g_xh);
    cudaGetSymbolAddress((void**)&xl, g_xl);
    cudaGetSymbolAddress((void**)&wqh, g_wqh);
    cudaGetSymbolAddress((void**)&wql, g_wql);
    cudaGetSymbolAddress((void**)&woh, g_woh);
    cudaGetSymbolAddress((void**)&wol, g_wol);
    cudaGetSymbolAddress((void**)&atth, g_atth);
    cudaGetSymbolAddress((void**)&attl, g_attl);

    cudaFuncSetAttribute(gemm_nt_bf16, cudaFuncAttributeMaxDynamicSharedMemorySize, GSM);
    cudaFuncSetAttribute(pv_bf16, cudaFuncAttributeMaxDynamicSharedMemorySize, PV_SM);

    split4<<<Nn * Cc / 4 / 256, 256>>>((const float4*)x, (bf162*)xh, (bf162*)xl, Nn * Cc / 4);
    split4<<<F3 * Cc / 4 / 256, 256>>>((const float4*)Wqkv, (bf162*)wqh, (bf162*)wql, F3 * Cc / 4);
    split4<<<Cc * Cc / 4 / 256, 256>>>((const float4*)Wout, (bf162*)woh, (bf162*)wol, Cc * Cc / 4);

    // qkv projection with fused scatter epilogue (mode 1)
    gemm_nt_bf16<<<dim3(F3 / 128, Nn / 128), 256, GSM>>>(xh, xl, wqh, wql, out, out, 1, Nn, F3, Cc);
    l2norm_k<<<2 * Hh * Nn * 32 / 256, 256>>>();
    vsum_part<<<dim3(Hh, 16), 256>>>();
    vsum_red<<<Hh, 64>>>();
    scores_bf16<<<dim3(136, Hh), 256>>>(tscale);
    premix_k<<<dim3(Nn / 256, Nn), 256>>>(Wpre, bpre, pb);
    rowred_k<<<Hh * Nn / 256, 256>>>();
    postmix_k<<<dim3(Nn / 256, Nn), 256>>>(Wpost);
    pv_bf16<<<dim3(Nn / 128, Hh), 256, PV_SM>>>(bpost);
    // output projection (mode 0)
    gemm_nt_bf16<<<dim3(Cc / 128, Nn / 128), 256, GSM>>>(atth, attl, woh, wol, out, out, 0, Nn, Cc, Cc);

    (void)in_sizes;
    (void)n_in;
    (void)out_size;
}